// round 14
// baseline (speedup 1.0000x reference)
#include <cuda_runtime.h>

#define B_      32
#define T_      512
#define D_      384
#define MAXOUT  3584                    // T_ * (8 - 1)
#define VEC     (D_ / 4)                // 96 float4 per row
#define THREADS 384                     // = 4 * VEC : no div/mod in hot loop
#define UNROLL  8
#define F4_PER_BLOCK (THREADS * UNROLL) // 3072 = exactly 32 rows
#define F4_PER_BATCH (MAXOUT * VEC)     // 344064
#define BLOCKS_PER_BATCH (F4_PER_BATCH / F4_PER_BLOCK) // 112, exact
#define NROWS   32                      // rows per block, exact (no straddle)

__global__ void __launch_bounds__(THREADS) lr_fused_kernel(
    const int*    __restrict__ dur,
    const float4* __restrict__ in,
    float4*       __restrict__ out)
{
    __shared__ int cum[T_];
    __shared__ int wsum[8];
    __shared__ int s_idx[NROWS];

    const int tid  = threadIdx.x;
    const int b    = blockIdx.y;
    const int lane = tid & 31;
    const int warp = tid >> 5;

    // ── Per-block recomputed inclusive scan (first 8 warps; 2 elems/thread) ──
    int v = 0, d1 = 0;
    if (tid < 256) {
        const int2 dp = ((const int2*)(dur + b * T_))[tid];
        const int  d0 = max(dp.x, 0);
        d1 = max(dp.y, 0);
        v  = d0 + d1;
        #pragma unroll
        for (int o = 1; o < 32; o <<= 1) {
            int n = __shfl_up_sync(0xffffffffu, v, o);
            if (lane >= o) v += n;
        }
        if (lane == 31) wsum[warp] = v;
    }
    __syncthreads();
    if (warp == 0) {
        int w = (lane < 8) ? wsum[lane] : 0;
        #pragma unroll
        for (int o = 1; o < 8; o <<= 1) {
            int n = __shfl_up_sync(0xffffffffu, w, o);
            if (lane >= o) w += n;
        }
        if (lane < 8) wsum[lane] = w;
    }
    __syncthreads();
    if (tid < 256) {
        const int incl = v + (warp > 0 ? wsum[warp - 1] : 0);
        cum[2 * tid + 1] = incl;
        cum[2 * tid]     = incl - d1;
    }
    __syncthreads();

    const int total    = cum[T_ - 1];
    const int f4_base  = blockIdx.x * F4_PER_BLOCK;
    const int row_base = blockIdx.x * NROWS;            // exact: 3072/96 = 32

    // ── One binary search per row of this block ──
    if (tid < NROWS) {
        const int row = row_base + tid;
        int idx = -1;
        if (row < total) {
            int p = 0;
            #pragma unroll
            for (int step = 256; step > 0; step >>= 1)
                if (cum[p + step - 1] <= row) p += step;
            idx = min(p, T_ - 1);
        }
        s_idx[tid] = idx;
    }
    __syncthreads();

    const int posb = f4_base + tid;
    const float4* __restrict__ inb  = in  + b * (T_ * VEC);
    float4*       __restrict__ outb = out + b * F4_PER_BATCH;

    if (row_base >= total) {
        // Entire block past the valid region: pure zero fill.
        const float4 z = make_float4(0.f, 0.f, 0.f, 0.f);
        #pragma unroll
        for (int j = 0; j < UNROLL; ++j)
            __stcs(&outb[posb + j * THREADS], z);
        return;
    }

    // Hot loop: col computed ONCE, row advances by exactly 4 per j step.
    const int rsub = tid / VEC;          // 0..3
    const int col  = tid - rsub * VEC;   // 0..95, constant across j

    int idx[UNROLL];
    #pragma unroll
    for (int j = 0; j < UNROLL; ++j)
        idx[j] = s_idx[rsub + 4 * j];    // one LDS each, no div/mod

    float4 val[UNROLL];
    #pragma unroll
    for (int j = 0; j < UNROLL; ++j) {
        const int ic = max(idx[j], 0);
        val[j] = __ldg(&inb[ic * VEC + col]);
    }

    #pragma unroll
    for (int j = 0; j < UNROLL; ++j) {
        float4 v4 = val[j];
        if (idx[j] < 0) v4 = make_float4(0.f, 0.f, 0.f, 0.f);
        __stcs(&outb[posb + j * THREADS], v4);
    }
}

extern "C" void kernel_launch(void* const* d_in, const int* in_sizes, int n_in,
                              void* d_out, int out_size)
{
    const float* x   = (const float*)d_in[0];   // [B, T, D] float32
    const int*   dur = (const int*)d_in[1];     // [B, T] int32
    float* out = (float*)d_out;                 // [B, MAXOUT, D] float32

    dim3 grid(BLOCKS_PER_BATCH, B_);
    lr_fused_kernel<<<grid, THREADS>>>(dur, (const float4*)x, (float4*)out);
}